// round 1
// baseline (speedup 1.0000x reference)
#include <cuda_runtime.h>
#include <math_constants.h>

#define N_TOK 4096
#define DIM   1024

// Scratch (allocation-free contract: __device__ globals)
__device__ float g_Q[(size_t)N_TOK * DIM];
__device__ float g_K[(size_t)N_TOK * DIM];
__device__ float g_S[(size_t)N_TOK * N_TOK];

// ---------------------------------------------------------------------------
// SGEMM: C[M,N] = alpha * A[M,K] * op(B)
//   TRANSB=false: B is [K,N] row-major (NN)
//   TRANSB=true : B is [N,K] row-major (NT, C = alpha*A*B^T)
// Block tile 128x128, K-tile 16, 256 threads, 8x8 per-thread microtile.
// All dims assumed multiples of 128 (true here: 4096, 1024).
// ---------------------------------------------------------------------------
template <bool TRANSB>
__global__ __launch_bounds__(256, 2)
void sgemm128(const float* __restrict__ A, const float* __restrict__ B,
              float* __restrict__ C, int M, int N, int K, float alpha)
{
    constexpr int BM = 128, BN = 128, BK = 16;
    __shared__ float As[BK][BM];   // transposed A tile: As[k][m]
    __shared__ float Bs[BK][BN];   // Bs[k][n]

    const int bx = blockIdx.x;     // along N
    const int by = blockIdx.y;     // along M
    const int tid = threadIdx.x;
    const int tx = tid & 15;       // 16 cols of threads
    const int ty = tid >> 4;       // 16 rows of threads

    float acc[8][8];
#pragma unroll
    for (int i = 0; i < 8; i++)
#pragma unroll
        for (int j = 0; j < 8; j++) acc[i][j] = 0.0f;

    for (int k0 = 0; k0 < K; k0 += BK) {
        // ---- load A tile (128 rows x 16 cols), store transposed ----
#pragma unroll
        for (int it = 0; it < 2; it++) {
            int idx  = tid + it * 256;      // float4 index 0..511
            int row  = idx >> 2;            // 0..127
            int col4 = idx & 3;             // 0..3
            const float4 v = *reinterpret_cast<const float4*>(
                &A[(size_t)(by * BM + row) * K + k0 + col4 * 4]);
            As[col4 * 4 + 0][row] = v.x;
            As[col4 * 4 + 1][row] = v.y;
            As[col4 * 4 + 2][row] = v.z;
            As[col4 * 4 + 3][row] = v.w;
        }
        // ---- load B tile ----
        if (TRANSB) {
            // B[N,K]: tile rows bx*128..+128, cols k0..+16 -> Bs[k][n]
#pragma unroll
            for (int it = 0; it < 2; it++) {
                int idx  = tid + it * 256;
                int row  = idx >> 2;
                int col4 = idx & 3;
                const float4 v = *reinterpret_cast<const float4*>(
                    &B[(size_t)(bx * BN + row) * K + k0 + col4 * 4]);
                Bs[col4 * 4 + 0][row] = v.x;
                Bs[col4 * 4 + 1][row] = v.y;
                Bs[col4 * 4 + 2][row] = v.z;
                Bs[col4 * 4 + 3][row] = v.w;
            }
        } else {
            // B[K,N]: tile rows k0..+16, cols bx*128..+128
#pragma unroll
            for (int it = 0; it < 2; it++) {
                int idx = tid + it * 256;   // float4 index over 16x32
                int row = idx >> 5;         // 0..15
                int c4  = idx & 31;         // 0..31
                const float4 v = *reinterpret_cast<const float4*>(
                    &B[(size_t)(k0 + row) * N + bx * BN + c4 * 4]);
                *reinterpret_cast<float4*>(&Bs[row][c4 * 4]) = v;
            }
        }
        __syncthreads();

        // ---- 8x8 microtile FMAs ----
#pragma unroll
        for (int k = 0; k < BK; k++) {
            float4 a0 = *reinterpret_cast<const float4*>(&As[k][ty * 4]);
            float4 a1 = *reinterpret_cast<const float4*>(&As[k][64 + ty * 4]);
            float4 b0 = *reinterpret_cast<const float4*>(&Bs[k][tx * 4]);
            float4 b1 = *reinterpret_cast<const float4*>(&Bs[k][64 + tx * 4]);
            float a[8] = {a0.x, a0.y, a0.z, a0.w, a1.x, a1.y, a1.z, a1.w};
            float b[8] = {b0.x, b0.y, b0.z, b0.w, b1.x, b1.y, b1.z, b1.w};
#pragma unroll
            for (int i = 0; i < 8; i++)
#pragma unroll
                for (int j = 0; j < 8; j++)
                    acc[i][j] = fmaf(a[i], b[j], acc[i][j]);
        }
        __syncthreads();
    }

    // ---- write back (float4, aligned) ----
#pragma unroll
    for (int ii = 0; ii < 2; ii++) {
#pragma unroll
        for (int i = 0; i < 4; i++) {
            int r = by * BM + ii * 64 + ty * 4 + i;
            float* Crow = C + (size_t)r * N + bx * BN;
            int ai = ii * 4 + i;
            float4 v0 = make_float4(alpha * acc[ai][0], alpha * acc[ai][1],
                                    alpha * acc[ai][2], alpha * acc[ai][3]);
            float4 v1 = make_float4(alpha * acc[ai][4], alpha * acc[ai][5],
                                    alpha * acc[ai][6], alpha * acc[ai][7]);
            *reinterpret_cast<float4*>(&Crow[tx * 4])      = v0;
            *reinterpret_cast<float4*>(&Crow[64 + tx * 4]) = v1;
        }
    }
}

// ---------------------------------------------------------------------------
// Row softmax in place over S[N_TOK, N_TOK]. One block per row, 256 threads,
// 16 elements per thread kept in registers (one global read, one write).
// ---------------------------------------------------------------------------
__global__ __launch_bounds__(256)
void softmax_rows(float* __restrict__ S)
{
    const int row = blockIdx.x;
    float* r = S + (size_t)row * N_TOK;
    const int tid = threadIdx.x;

    float v[16];
    float m = -CUDART_INF_F;
#pragma unroll
    for (int i = 0; i < 16; i++) {
        v[i] = r[tid + i * 256];
        m = fmaxf(m, v[i]);
    }

    __shared__ float red[8];
    // block max
#pragma unroll
    for (int o = 16; o > 0; o >>= 1)
        m = fmaxf(m, __shfl_xor_sync(0xffffffffu, m, o));
    if ((tid & 31) == 0) red[tid >> 5] = m;
    __syncthreads();
    m = red[0];
#pragma unroll
    for (int w = 1; w < 8; w++) m = fmaxf(m, red[w]);

    float sum = 0.0f;
#pragma unroll
    for (int i = 0; i < 16; i++) {
        v[i] = expf(v[i] - m);
        sum += v[i];
    }
    __syncthreads();
#pragma unroll
    for (int o = 16; o > 0; o >>= 1)
        sum += __shfl_xor_sync(0xffffffffu, sum, o);
    if ((tid & 31) == 0) red[tid >> 5] = sum;
    __syncthreads();
    sum = 0.0f;
#pragma unroll
    for (int w = 0; w < 8; w++) sum += red[w];

    const float inv = 1.0f / sum;
#pragma unroll
    for (int i = 0; i < 16; i++)
        r[tid + i * 256] = v[i] * inv;
}

// ---------------------------------------------------------------------------
extern "C" void kernel_launch(void* const* d_in, const int* in_sizes, int n_in,
                              void* d_out, int out_size)
{
    const float* X  = (const float*)d_in[0];  // [4096,1024]
    const float* Wq = (const float*)d_in[1];  // [1024,1024]
    const float* Wk = (const float*)d_in[2];  // [1024,1024]
    float* O = (float*)d_out;                 // [4096,1024]

    float *Q, *K, *S;
    cudaGetSymbolAddress((void**)&Q, g_Q);
    cudaGetSymbolAddress((void**)&K, g_K);
    cudaGetSymbolAddress((void**)&S, g_S);

    const float scale = 0.03125f; // 1/sqrt(1024)

    // Q = X @ Wq   (NN: M=4096 N=1024 K=1024)
    sgemm128<false><<<dim3(DIM / 128, N_TOK / 128), 256>>>(X, Wq, Q, N_TOK, DIM, DIM, 1.0f);
    // K = X @ Wk
    sgemm128<false><<<dim3(DIM / 128, N_TOK / 128), 256>>>(X, Wk, K, N_TOK, DIM, DIM, 1.0f);
    // S = (Q @ K^T) * scale   (NT: M=N=4096, K=1024)
    sgemm128<true><<<dim3(N_TOK / 128, N_TOK / 128), 256>>>(Q, K, S, N_TOK, N_TOK, DIM, scale);
    // softmax rows
    softmax_rows<<<N_TOK, 256>>>(S);
    // O = S @ X   (NN: M=4096 N=1024 K=4096)
    sgemm128<false><<<dim3(DIM / 128, N_TOK / 128), 256>>>(S, X, O, N_TOK, DIM, N_TOK, 1.0f);
}